// round 7
// baseline (speedup 1.0000x reference)
#include <cuda_runtime.h>
#include <cuda_bf16.h>
#include <cuda_fp16.h>
#include <cstdint>

#define BB 4
#define SS 4096
#define DD 512
#define BSD (BB*SS*DD)      // 8388608

// ---------------- device scratch (static; no allocations allowed) -------------
__device__ __nv_bfloat16 g_xhi[BSD];
__device__ __nv_bfloat16 g_xlo[BSD];
__device__ __nv_bfloat16 g_KQ[(size_t)BB*SS*2*DD];     // [16384, 1024] = K|Q
__device__ __half        g_E[(size_t)BB*SS*SS];        // 128MB
__device__ float         g_cpart[(size_t)BB*32*SS];    // per-row-tile column partials
__device__ float         g_rc[BB*SS];   // 1/colsum
__device__ float         g_rs[BB*SS];   // rowsum
__device__ __nv_bfloat16 g_Wkq[2*DD*DD];
__device__ float         g_bkq[2*DD];
__device__ __nv_bfloat16 g_Mhi[DD*DD], g_Mlo[DD*DD];   // M = Wl @ Wv, hi/lo split
__device__ float         g_c[DD];                      // c = Wl @ bv

// ---------------- helpers ----------------------------------------------------
__device__ __forceinline__ unsigned sptr(const void* p){
    return (unsigned)__cvta_generic_to_shared(p);
}
__device__ __forceinline__ void ldm4(unsigned r[4], unsigned addr){
    asm volatile("ldmatrix.sync.aligned.m8n8.x4.shared.b16 {%0,%1,%2,%3}, [%4];"
        : "=r"(r[0]),"=r"(r[1]),"=r"(r[2]),"=r"(r[3]) : "r"(addr));
}
__device__ __forceinline__ void mma16816(float c[4], const unsigned a[4], const unsigned b[2]){
    asm volatile("mma.sync.aligned.m16n8k16.row.col.f32.bf16.bf16.f32 "
        "{%0,%1,%2,%3},{%4,%5,%6,%7},{%8,%9},{%0,%1,%2,%3};"
        : "+f"(c[0]),"+f"(c[1]),"+f"(c[2]),"+f"(c[3])
        : "r"(a[0]),"r"(a[1]),"r"(a[2]),"r"(a[3]),"r"(b[0]),"r"(b[1]));
}

// ---------------- prep: x hi/lo split + KQ weight stack -----------------------
__global__ void prep_kernel(const float* __restrict__ xs, const float* __restrict__ Wk,
                            const float* __restrict__ Wq, const float* __restrict__ bk,
                            const float* __restrict__ bq){
    long i = (long)blockIdx.x*blockDim.x + threadIdx.x;
    if (i < (long)BSD){
        float v = xs[i];
        __nv_bfloat16 h = __float2bfloat16(v);
        g_xhi[i] = h;
        g_xlo[i] = __float2bfloat16(v - __bfloat162float(h));
    }
    if (i < DD*DD){
        g_Wkq[i]         = __float2bfloat16(Wk[i]);
        g_Wkq[DD*DD + i] = __float2bfloat16(Wq[i]);
    }
    if (i < DD){
        g_bkq[i] = bk[i]; g_bkq[DD + i] = bq[i];
    }
}

// ---------------- M = Wl @ Wv (fp32 tiled) -> hi/lo bf16 split ----------------
__global__ void matM_kernel(const float* __restrict__ Wl, const float* __restrict__ Wv){
    __shared__ float sA[16][16], sB[16][17];
    int tx = threadIdx.x, ty = threadIdx.y;
    int e = blockIdx.y*16 + ty, d = blockIdx.x*16 + tx;
    float acc = 0.f;
    for (int t0 = 0; t0 < DD; t0 += 16){
        sA[ty][tx] = Wl[e*DD + t0 + tx];
        sB[ty][tx] = Wv[(t0 + ty)*DD + d];
        __syncthreads();
        #pragma unroll
        for (int t = 0; t < 16; t++) acc += sA[ty][t]*sB[t][tx];
        __syncthreads();
    }
    __nv_bfloat16 h = __float2bfloat16(acc);
    g_Mhi[e*DD + d] = h;
    g_Mlo[e*DD + d] = __float2bfloat16(acc - __bfloat162float(h));
}

// ---------------- c = Wl @ bv (one warp per output) ---------------------------
__global__ void cvec_kernel(const float* __restrict__ Wl, const float* __restrict__ bv){
    int e = blockIdx.x*8 + (threadIdx.x >> 5), lane = threadIdx.x & 31;
    float s = 0.f;
    for (int d = lane; d < DD; d += 32) s += Wl[e*DD + d]*bv[d];
    #pragma unroll
    for (int o = 16; o; o >>= 1) s += __shfl_xor_sync(0xffffffffu, s, o);
    if (lane == 0) g_c[e] = s;
}

// ---------------- generic C = A * B^T GEMM (round-3 proven mainloop) ----------
// EPI: 0 bf16+bias (K|Q proj)
//      2 exp->fp16 E + fp16-rounded column partials (QK)
//      4 tanh(rs*(acc + c) + bias) -> fp32 (final fused output)
// SPLIT: 3-product hi/lo accumulation.
constexpr int Bb_M = 128, Bb_N = 128, Bb_K = 32, LDS = 40;

template<int EPI, bool SPLIT>
__global__ void __launch_bounds__(256)
gemm_kernel(const __nv_bfloat16* __restrict__ A, const __nv_bfloat16* __restrict__ A2,
            const __nv_bfloat16* __restrict__ B, const __nv_bfloat16* __restrict__ B2,
            const float* __restrict__ bias, void* __restrict__ Cout,
            int Kd, int lda, int ldb, int ldc,
            long batchA, long batchB, long batchC,
            const float* __restrict__ rsG, const float* __restrict__ cG)
{
    extern __shared__ __nv_bfloat16 sm[];
    constexpr int AR = Bb_M*LDS;
    __nv_bfloat16* As  = sm;
    __nv_bfloat16* Bs  = sm + AR;
    __nv_bfloat16* As2 = SPLIT ? sm + 2*AR : nullptr;
    __nv_bfloat16* Bs2 = SPLIT ? sm + 3*AR : nullptr;

    int z = blockIdx.z;
    const __nv_bfloat16* Ag  = A + z*batchA;
    const __nv_bfloat16* Bg  = B + z*batchB;
    const __nv_bfloat16* A2g = SPLIT ? A2 + z*batchA : nullptr;
    const __nv_bfloat16* B2g = SPLIT ? B2 + z*batchB : nullptr;

    int tid = threadIdx.x, lane = tid & 31, warp = tid >> 5;
    int wm = warp >> 2, wn = warp & 3;           // 2x4 warp grid -> 64x32 per warp
    int bm0 = blockIdx.y * Bb_M, bn0 = blockIdx.x * Bb_N;
    int lr = tid >> 1;                            // loader row 0..127
    int lc = (tid & 1) * 8;                       // loader col (halfs)

    float acc[4][4][4] = {};

    for (int k0 = 0; k0 < Kd; k0 += Bb_K){
        {
            const __nv_bfloat16* a = Ag + (long)(bm0+lr)*lda + k0 + lc;
            *(uint4*)(As + lr*LDS + lc)      = *(const uint4*)(a);
            *(uint4*)(As + lr*LDS + lc + 16) = *(const uint4*)(a + 16);
            if (SPLIT){
                const __nv_bfloat16* a2 = A2g + (long)(bm0+lr)*lda + k0 + lc;
                *(uint4*)(As2 + lr*LDS + lc)      = *(const uint4*)(a2);
                *(uint4*)(As2 + lr*LDS + lc + 16) = *(const uint4*)(a2 + 16);
            }
            const __nv_bfloat16* b = Bg + (long)(bn0+lr)*ldb + k0 + lc;
            *(uint4*)(Bs + lr*LDS + lc)      = *(const uint4*)(b);
            *(uint4*)(Bs + lr*LDS + lc + 16) = *(const uint4*)(b + 16);
            if (SPLIT){
                const __nv_bfloat16* b2 = B2g + (long)(bn0+lr)*ldb + k0 + lc;
                *(uint4*)(Bs2 + lr*LDS + lc)      = *(const uint4*)(b2);
                *(uint4*)(Bs2 + lr*LDS + lc + 16) = *(const uint4*)(b2 + 16);
            }
        }
        __syncthreads();

        #pragma unroll
        for (int kk = 0; kk < Bb_K; kk += 16){
            unsigned af[4][4], bf[4][2];
            unsigned af2[4][4], bf2[4][2];
            int arow = wm*64 + (lane & 15);
            int acol = kk + 8*(lane >> 4);
            #pragma unroll
            for (int mi=0; mi<4; mi++){
                ldm4(af[mi],  sptr(As  + (arow + mi*16)*LDS + acol));
                if (SPLIT) ldm4(af2[mi], sptr(As2 + (arow + mi*16)*LDS + acol));
            }
            int brow = wn*32 + (lane & 7) + ((lane & 16) ? 8 : 0);
            int bcol = kk + ((lane & 8) ? 8 : 0);
            #pragma unroll
            for (int nb=0; nb<2; nb++){
                unsigned tmp[4];
                ldm4(tmp, sptr(Bs + (brow + nb*16)*LDS + bcol));
                bf[2*nb][0]=tmp[0]; bf[2*nb][1]=tmp[1];
                bf[2*nb+1][0]=tmp[2]; bf[2*nb+1][1]=tmp[3];
                if (SPLIT){
                    ldm4(tmp, sptr(Bs2 + (brow + nb*16)*LDS + bcol));
                    bf2[2*nb][0]=tmp[0]; bf2[2*nb][1]=tmp[1];
                    bf2[2*nb+1][0]=tmp[2]; bf2[2*nb+1][1]=tmp[3];
                }
            }
            #pragma unroll
            for (int mi=0; mi<4; mi++)
                #pragma unroll
                for (int ni=0; ni<4; ni++){
                    mma16816(acc[mi][ni], af[mi], bf[ni]);
                    if (SPLIT){
                        mma16816(acc[mi][ni], af[mi],  bf2[ni]);
                        mma16816(acc[mi][ni], af2[mi], bf[ni]);
                    }
                }
        }
        __syncthreads();
    }

    // ---------------- epilogue ----------------
    int tr = lane >> 2, tc = (lane & 3) * 2;
    if (EPI == 2){
        __half* C = (__half*)Cout + z*batchC;
        const float inv = 1.0f/512.0f;
        float csum[4][2];
        #pragma unroll
        for (int ni=0; ni<4; ni++){ csum[ni][0]=0.f; csum[ni][1]=0.f; }
        #pragma unroll
        for (int mi=0; mi<4; mi++){
            #pragma unroll
            for (int ni=0; ni<4; ni++){
                int row = bm0 + wm*64 + mi*16 + tr;
                int col = bn0 + wn*32 + ni*8 + tc;
                float* a = acc[mi][ni];
                // round to fp16 FIRST, then sum the rounded value -> colsum and
                // rowsum see identical quantization (error cancels in the ratio)
                __half h0 = __float2half_rn(__expf(a[0]*inv));
                __half h1 = __float2half_rn(__expf(a[1]*inv));
                __half h2 = __float2half_rn(__expf(a[2]*inv));
                __half h3 = __float2half_rn(__expf(a[3]*inv));
                *(__half2*)(C + (long)row*ldc + col)     = __halves2half2(h0, h1);
                *(__half2*)(C + (long)(row+8)*ldc + col) = __halves2half2(h2, h3);
                csum[ni][0] += __half2float(h0) + __half2float(h2);
                csum[ni][1] += __half2float(h1) + __half2float(h3);
            }
        }
        #pragma unroll
        for (int ni=0; ni<4; ni++)
            #pragma unroll
            for (int j=0; j<2; j++){
                float s = csum[ni][j];
                s += __shfl_xor_sync(0xffffffffu, s, 4);
                s += __shfl_xor_sync(0xffffffffu, s, 8);
                s += __shfl_xor_sync(0xffffffffu, s, 16);
                csum[ni][j] = s;
            }
        float* cps = (float*)sm;   // smem reuse: all compute done (sync at loop end)
        if (lane < 4){
            #pragma unroll
            for (int ni=0; ni<4; ni++){
                cps[wm*128 + wn*32 + ni*8 + tc]     = csum[ni][0];
                cps[wm*128 + wn*32 + ni*8 + tc + 1] = csum[ni][1];
            }
        }
        __syncthreads();
        if (tid < 128)
            g_cpart[((long)z*32 + blockIdx.y)*SS + bn0 + tid] = cps[tid] + cps[128 + tid];
        return;
    }
    #pragma unroll
    for (int mi=0; mi<4; mi++){
        #pragma unroll
        for (int ni=0; ni<4; ni++){
            int row = bm0 + wm*64 + mi*16 + tr;
            int col = bn0 + wn*32 + ni*8 + tc;
            float* a = acc[mi][ni];
            if (EPI == 0){
                __nv_bfloat16* C = (__nv_bfloat16*)Cout;
                float b0 = bias[col], b1 = bias[col+1];
                *(__nv_bfloat162*)(C + (long)row*ldc + col)     = __floats2bfloat162_rn(a[0]+b0, a[1]+b1);
                *(__nv_bfloat162*)(C + (long)(row+8)*ldc + col) = __floats2bfloat162_rn(a[2]+b0, a[3]+b1);
            } else {  // EPI == 4: out = tanh(rs*(acc + c) + bl)
                float* C = (float*)Cout;
                float b0 = bias[col], b1 = bias[col+1];
                float c0 = cG[col],  c1 = cG[col+1];
                float r0 = rsG[row], r8 = rsG[row+8];
                *(float2*)(C + (long)row*ldc + col) =
                    make_float2(tanhf(r0*(a[0]+c0)+b0), tanhf(r0*(a[1]+c1)+b1));
                *(float2*)(C + (long)(row+8)*ldc + col) =
                    make_float2(tanhf(r8*(a[2]+c0)+b0), tanhf(r8*(a[3]+c1)+b1));
            }
        }
    }
}

// ---------------- rc[b,e] = 1 / sum of column partials ------------------------
__global__ void __launch_bounds__(256) rc_kernel(){
    int i = blockIdx.x*256 + threadIdx.x;       // 0..16383
    int b = i >> 12, e = i & (SS-1);
    const float* p = g_cpart + (long)b*32*SS + e;
    float s = 0.f;
    #pragma unroll
    for (int t = 0; t < 32; t++) s += p[(long)t*SS];
    g_rc[i] = 1.0f/s;
}

// ---------------- rowsum: rs[b,s] = sum_e E[b,s,e] * rc[b,e] ------------------
__global__ void __launch_bounds__(256) rowsum_kernel(){
    __shared__ float rcs[SS];
    int b = blockIdx.y;
    for (int i = threadIdx.x; i < SS; i += 256) rcs[i] = g_rc[b*SS + i];
    __syncthreads();
    int lane = threadIdx.x & 31, warp = threadIdx.x >> 5;
    int r0 = blockIdx.x*64 + warp*8;
    for (int k = 0; k < 8; k++){
        int r = r0 + k;
        const __half2* row = (const __half2*)(g_E + ((long)b*SS + r)*(long)SS);
        float s = 0.f;
        for (int j = lane; j < SS/2; j += 32){
            float2 f = __half22float2(row[j]);
            s += f.x*rcs[2*j] + f.y*rcs[2*j+1];
        }
        #pragma unroll
        for (int o = 16; o; o >>= 1) s += __shfl_xor_sync(0xffffffffu, s, o);
        if (lane == 0) g_rs[b*SS + r] = s;
    }
}

// ---------------- launch -----------------------------------------------------
extern "C" void kernel_launch(void* const* d_in, const int* in_sizes, int n_in,
                              void* d_out, int out_size)
{
    const float* xs = (const float*)d_in[0];
    const float* Wk = (const float*)d_in[1]; const float* bk = (const float*)d_in[2];
    const float* Wq = (const float*)d_in[3]; const float* bq = (const float*)d_in[4];
    const float* Wv = (const float*)d_in[5]; const float* bv = (const float*)d_in[6];
    const float* Wl = (const float*)d_in[7]; const float* bl = (const float*)d_in[8];

    void *p_xhi,*p_xlo,*p_KQ,*p_E,*p_bkq,*p_Wkq;
    void *p_Mhi,*p_Mlo,*p_rs,*p_c;
    cudaGetSymbolAddress(&p_xhi, g_xhi);   cudaGetSymbolAddress(&p_xlo, g_xlo);
    cudaGetSymbolAddress(&p_KQ,  g_KQ);    cudaGetSymbolAddress(&p_E,   g_E);
    cudaGetSymbolAddress(&p_bkq, g_bkq);   cudaGetSymbolAddress(&p_Wkq, g_Wkq);
    cudaGetSymbolAddress(&p_Mhi, g_Mhi);   cudaGetSymbolAddress(&p_Mlo, g_Mlo);
    cudaGetSymbolAddress(&p_rs,  g_rs);    cudaGetSymbolAddress(&p_c,   g_c);

    constexpr int AR = Bb_M*LDS;
    const size_t smemPlain = (size_t)2*AR*sizeof(__nv_bfloat16);   // 20480
    const size_t smemSplit = (size_t)4*AR*sizeof(__nv_bfloat16);   // 40960

    // 1. prep (x split, K|Q weight stack) + M = Wl@Wv split + c = Wl@bv
    prep_kernel<<<(BSD + 255)/256, 256>>>(xs, Wk, Wq, bk, bq);
    matM_kernel<<<dim3(DD/16, DD/16), dim3(16,16)>>>(Wl, Wv);
    cvec_kernel<<<DD/8, 256>>>(Wl, bv);

    // 2. merged K|Q projection -> g_KQ [16384, 1024]
    dim3 gkq(2*DD/Bb_N, (BB*SS)/Bb_M, 1);   // (8, 128)
    gemm_kernel<0,false><<<gkq, 256, smemPlain>>>(
        (const __nv_bfloat16*)p_xhi, nullptr, (const __nv_bfloat16*)p_Wkq, nullptr,
        (const float*)p_bkq, p_KQ, DD, DD, DD, 2*DD, 0, 0, 0, nullptr, nullptr);

    // 3. E = exp(K Q^T / 512) fp16 + fused fp16-rounded column partials
    dim3 gq(SS/Bb_N, SS/Bb_M, BB);          // (32, 32, 4)
    gemm_kernel<2,false><<<gq, 256, smemPlain>>>(
        (const __nv_bfloat16*)p_KQ, nullptr,
        (const __nv_bfloat16*)p_KQ + DD, nullptr,
        nullptr, p_E, DD, 2*DD, 2*DD, SS,
        (long)SS*2*DD, (long)SS*2*DD, (long)SS*SS, nullptr, nullptr);

    // 4. rc = 1/colsum; 5. rowsum
    rc_kernel<<<BB*SS/256, 256>>>();
    rowsum_kernel<<<dim3(SS/64, BB), 256>>>();

    // 6. out = tanh(rs*(x M^T + c) + bl)  — single fused split GEMM
    dim3 gp(DD/Bb_N, (BB*SS)/Bb_M, 1);      // (4, 128)
    gemm_kernel<4,true><<<gp, 256, smemSplit>>>(
        (const __nv_bfloat16*)p_xhi, (const __nv_bfloat16*)p_xlo,
        (const __nv_bfloat16*)p_Mhi, (const __nv_bfloat16*)p_Mlo,
        bl, d_out, DD, DD, DD, DD, 0, 0, 0,
        (const float*)p_rs, (const float*)p_c);
}

// round 8
// speedup vs baseline: 1.0963x; 1.0963x over previous
#include <cuda_runtime.h>
#include <cuda_bf16.h>
#include <cuda_fp16.h>
#include <cstdint>

#define BB 4
#define SS 4096
#define DD 512
#define BSD (BB*SS*DD)      // 8388608

// ---------------- device scratch (static; no allocations allowed) -------------
__device__ __nv_bfloat16 g_xhi[BSD];
__device__ __nv_bfloat16 g_xlo[BSD];
__device__ __nv_bfloat16 g_KQ[(size_t)BB*SS*2*DD];     // [16384, 1024] = K|Q
__device__ __half        g_E[(size_t)BB*SS*SS];        // 128MB
__device__ float         g_cpart[(size_t)BB*32*SS];    // per-row-tile column partials
__device__ float         g_rc[BB*SS];   // 1/colsum
__device__ float         g_rs[BB*SS];   // rowsum
__device__ __nv_bfloat16 g_Wkq[2*DD*DD];
__device__ float         g_bkq[2*DD];
__device__ __nv_bfloat16 g_Mhi[DD*DD], g_Mlo[DD*DD];   // M = Wl @ Wv, hi/lo split
__device__ float         g_c[DD];                      // c = Wl @ bv

// ---------------- helpers ----------------------------------------------------
__device__ __forceinline__ unsigned sptr(const void* p){
    return (unsigned)__cvta_generic_to_shared(p);
}
__device__ __forceinline__ void ldm4(unsigned r[4], unsigned addr){
    asm volatile("ldmatrix.sync.aligned.m8n8.x4.shared.b16 {%0,%1,%2,%3}, [%4];"
        : "=r"(r[0]),"=r"(r[1]),"=r"(r[2]),"=r"(r[3]) : "r"(addr));
}
__device__ __forceinline__ void mma16816(float c[4], const unsigned a[4], const unsigned b[2]){
    asm volatile("mma.sync.aligned.m16n8k16.row.col.f32.bf16.bf16.f32 "
        "{%0,%1,%2,%3},{%4,%5,%6,%7},{%8,%9},{%0,%1,%2,%3};"
        : "+f"(c[0]),"+f"(c[1]),"+f"(c[2]),"+f"(c[3])
        : "r"(a[0]),"r"(a[1]),"r"(a[2]),"r"(a[3]),"r"(b[0]),"r"(b[1]));
}

// ---------------- prep: x hi/lo split + KQ weight stack -----------------------
__global__ void prep_kernel(const float* __restrict__ xs, const float* __restrict__ Wk,
                            const float* __restrict__ Wq, const float* __restrict__ bk,
                            const float* __restrict__ bq){
    long i = (long)blockIdx.x*blockDim.x + threadIdx.x;
    if (i < (long)BSD){
        float v = xs[i];
        __nv_bfloat16 h = __float2bfloat16(v);
        g_xhi[i] = h;
        g_xlo[i] = __float2bfloat16(v - __bfloat162float(h));
    }
    if (i < DD*DD){
        g_Wkq[i]         = __float2bfloat16(Wk[i]);
        g_Wkq[DD*DD + i] = __float2bfloat16(Wq[i]);
    }
    if (i < DD){
        g_bkq[i] = bk[i]; g_bkq[DD + i] = bq[i];
    }
}

// ---------------- M = Wl @ Wv (fp32 tiled) -> hi/lo bf16 split ----------------
__global__ void matM_kernel(const float* __restrict__ Wl, const float* __restrict__ Wv){
    __shared__ float sA[16][16], sB[16][17];
    int tx = threadIdx.x, ty = threadIdx.y;
    int e = blockIdx.y*16 + ty, d = blockIdx.x*16 + tx;
    float acc = 0.f;
    for (int t0 = 0; t0 < DD; t0 += 16){
        sA[ty][tx] = Wl[e*DD + t0 + tx];
        sB[ty][tx] = Wv[(t0 + ty)*DD + d];
        __syncthreads();
        #pragma unroll
        for (int t = 0; t < 16; t++) acc += sA[ty][t]*sB[t][tx];
        __syncthreads();
    }
    __nv_bfloat16 h = __float2bfloat16(acc);
    g_Mhi[e*DD + d] = h;
    g_Mlo[e*DD + d] = __float2bfloat16(acc - __bfloat162float(h));
}

// ---------------- c = Wl @ bv (one warp per output) ---------------------------
__global__ void cvec_kernel(const float* __restrict__ Wl, const float* __restrict__ bv){
    int e = blockIdx.x*8 + (threadIdx.x >> 5), lane = threadIdx.x & 31;
    float s = 0.f;
    for (int d = lane; d < DD; d += 32) s += Wl[e*DD + d]*bv[d];
    #pragma unroll
    for (int o = 16; o; o >>= 1) s += __shfl_xor_sync(0xffffffffu, s, o);
    if (lane == 0) g_c[e] = s;
}

// ---------------- generic C = A * B^T GEMM ------------------------------------
// EPI: 0 bf16+bias (K|Q proj)
//      2 exp->fp16 E + fp16-rounded column partials (QK)
//      4 tanh(rs*(acc + c) + bias) -> fp32 (final fused output)
// SPLIT: 3-product hi/lo accumulation.
constexpr int Bb_M = 128, Bb_N = 128, Bb_K = 64, LDS = 72;  // Bb_K 32->64

template<int EPI, bool SPLIT>
__global__ void __launch_bounds__(256)
gemm_kernel(const __nv_bfloat16* __restrict__ A, const __nv_bfloat16* __restrict__ A2,
            const __nv_bfloat16* __restrict__ B, const __nv_bfloat16* __restrict__ B2,
            const float* __restrict__ bias, void* __restrict__ Cout,
            int Kd, int lda, int ldb, int ldc,
            long batchA, long batchB, long batchC,
            const float* __restrict__ rsG, const float* __restrict__ cG)
{
    extern __shared__ __nv_bfloat16 sm[];
    constexpr int AR = Bb_M*LDS;
    __nv_bfloat16* As  = sm;
    __nv_bfloat16* Bs  = sm + AR;
    __nv_bfloat16* As2 = SPLIT ? sm + 2*AR : nullptr;
    __nv_bfloat16* Bs2 = SPLIT ? sm + 3*AR : nullptr;

    int z = blockIdx.z;
    const __nv_bfloat16* Ag  = A + z*batchA;
    const __nv_bfloat16* Bg  = B + z*batchB;
    const __nv_bfloat16* A2g = SPLIT ? A2 + z*batchA : nullptr;
    const __nv_bfloat16* B2g = SPLIT ? B2 + z*batchB : nullptr;

    int tid = threadIdx.x, lane = tid & 31, warp = tid >> 5;
    int wm = warp >> 2, wn = warp & 3;           // 2x4 warp grid -> 64x32 per warp
    int bm0 = blockIdx.y * Bb_M, bn0 = blockIdx.x * Bb_N;
    int lr = tid >> 1;                            // loader row 0..127
    int lc = (tid & 1) * 8;                       // loader col base (halfs)

    float acc[4][4][4] = {};

    for (int k0 = 0; k0 < Kd; k0 += Bb_K){
        {
            const __nv_bfloat16* a = Ag + (long)(bm0+lr)*lda + k0 + lc;
            __nv_bfloat16* da = As + lr*LDS + lc;
            *(uint4*)(da)      = *(const uint4*)(a);
            *(uint4*)(da + 16) = *(const uint4*)(a + 16);
            *(uint4*)(da + 32) = *(const uint4*)(a + 32);
            *(uint4*)(da + 48) = *(const uint4*)(a + 48);
            const __nv_bfloat16* b = Bg + (long)(bn0+lr)*ldb + k0 + lc;
            __nv_bfloat16* db = Bs + lr*LDS + lc;
            *(uint4*)(db)      = *(const uint4*)(b);
            *(uint4*)(db + 16) = *(const uint4*)(b + 16);
            *(uint4*)(db + 32) = *(const uint4*)(b + 32);
            *(uint4*)(db + 48) = *(const uint4*)(b + 48);
            if (SPLIT){
                const __nv_bfloat16* a2 = A2g + (long)(bm0+lr)*lda + k0 + lc;
                __nv_bfloat16* da2 = As2 + lr*LDS + lc;
                *(uint4*)(da2)      = *(const uint4*)(a2);
                *(uint4*)(da2 + 16) = *(const uint4*)(a2 + 16);
                *(uint4*)(da2 + 32) = *(const uint4*)(a2 + 32);
                *(uint4*)(da2 + 48) = *(const uint4*)(a2 + 48);
                const __nv_bfloat16* b2 = B2g + (long)(bn0+lr)*ldb + k0 + lc;
                __nv_bfloat16* db2 = Bs2 + lr*LDS + lc;
                *(uint4*)(db2)      = *(const uint4*)(b2);
                *(uint4*)(db2 + 16) = *(const uint4*)(b2 + 16);
                *(uint4*)(db2 + 32) = *(const uint4*)(b2 + 32);
                *(uint4*)(db2 + 48) = *(const uint4*)(b2 + 48);
            }
        }
        __syncthreads();

        #pragma unroll
        for (int kk = 0; kk < Bb_K; kk += 16){
            unsigned af[4][4], bf[4][2];
            unsigned af2[4][4], bf2[4][2];
            int arow = wm*64 + (lane & 15);
            int acol = kk + 8*(lane >> 4);
            #pragma unroll
            for (int mi=0; mi<4; mi++){
                ldm4(af[mi],  sptr(As  + (arow + mi*16)*LDS + acol));
                if (SPLIT) ldm4(af2[mi], sptr(As2 + (arow + mi*16)*LDS + acol));
            }
            int brow = wn*32 + (lane & 7) + ((lane & 16) ? 8 : 0);
            int bcol = kk + ((lane & 8) ? 8 : 0);
            #pragma unroll
            for (int nb=0; nb<2; nb++){
                unsigned tmp[4];
                ldm4(tmp, sptr(Bs + (brow + nb*16)*LDS + bcol));
                bf[2*nb][0]=tmp[0]; bf[2*nb][1]=tmp[1];
                bf[2*nb+1][0]=tmp[2]; bf[2*nb+1][1]=tmp[3];
                if (SPLIT){
                    ldm4(tmp, sptr(Bs2 + (brow + nb*16)*LDS + bcol));
                    bf2[2*nb][0]=tmp[0]; bf2[2*nb][1]=tmp[1];
                    bf2[2*nb+1][0]=tmp[2]; bf2[2*nb+1][1]=tmp[3];
                }
            }
            #pragma unroll
            for (int mi=0; mi<4; mi++)
                #pragma unroll
                for (int ni=0; ni<4; ni++){
                    mma16816(acc[mi][ni], af[mi], bf[ni]);
                    if (SPLIT){
                        mma16816(acc[mi][ni], af[mi],  bf2[ni]);
                        mma16816(acc[mi][ni], af2[mi], bf[ni]);
                    }
                }
        }
        __syncthreads();
    }

    // ---------------- epilogue ----------------
    int tr = lane >> 2, tc = (lane & 3) * 2;
    if (EPI == 2){
        __half* C = (__half*)Cout + z*batchC;
        const float inv = 1.0f/512.0f;
        float csum[4][2];
        #pragma unroll
        for (int ni=0; ni<4; ni++){ csum[ni][0]=0.f; csum[ni][1]=0.f; }
        #pragma unroll
        for (int mi=0; mi<4; mi++){
            #pragma unroll
            for (int ni=0; ni<4; ni++){
                int row = bm0 + wm*64 + mi*16 + tr;
                int col = bn0 + wn*32 + ni*8 + tc;
                float* a = acc[mi][ni];
                // round to fp16 FIRST, then sum the rounded value -> colsum and
                // rowsum see identical quantization (error cancels in the ratio)
                __half h0 = __float2half_rn(__expf(a[0]*inv));
                __half h1 = __float2half_rn(__expf(a[1]*inv));
                __half h2 = __float2half_rn(__expf(a[2]*inv));
                __half h3 = __float2half_rn(__expf(a[3]*inv));
                *(__half2*)(C + (long)row*ldc + col)     = __halves2half2(h0, h1);
                *(__half2*)(C + (long)(row+8)*ldc + col) = __halves2half2(h2, h3);
                csum[ni][0] += __half2float(h0) + __half2float(h2);
                csum[ni][1] += __half2float(h1) + __half2float(h3);
            }
        }
        #pragma unroll
        for (int ni=0; ni<4; ni++)
            #pragma unroll
            for (int j=0; j<2; j++){
                float s = csum[ni][j];
                s += __shfl_xor_sync(0xffffffffu, s, 4);
                s += __shfl_xor_sync(0xffffffffu, s, 8);
                s += __shfl_xor_sync(0xffffffffu, s, 16);
                csum[ni][j] = s;
            }
        float* cps = (float*)sm;   // smem reuse: all compute done (sync at loop end)
        if (lane < 4){
            #pragma unroll
            for (int ni=0; ni<4; ni++){
                cps[wm*128 + wn*32 + ni*8 + tc]     = csum[ni][0];
                cps[wm*128 + wn*32 + ni*8 + tc + 1] = csum[ni][1];
            }
        }
        __syncthreads();
        if (tid < 128)
            g_cpart[((long)z*32 + blockIdx.y)*SS + bn0 + tid] = cps[tid] + cps[128 + tid];
        return;
    }
    #pragma unroll
    for (int mi=0; mi<4; mi++){
        #pragma unroll
        for (int ni=0; ni<4; ni++){
            int row = bm0 + wm*64 + mi*16 + tr;
            int col = bn0 + wn*32 + ni*8 + tc;
            float* a = acc[mi][ni];
            if (EPI == 0){
                __nv_bfloat16* C = (__nv_bfloat16*)Cout;
                float b0 = bias[col], b1 = bias[col+1];
                *(__nv_bfloat162*)(C + (long)row*ldc + col)     = __floats2bfloat162_rn(a[0]+b0, a[1]+b1);
                *(__nv_bfloat162*)(C + (long)(row+8)*ldc + col) = __floats2bfloat162_rn(a[2]+b0, a[3]+b1);
            } else {  // EPI == 4: out = tanh(rs*(acc + c) + bl)
                float* C = (float*)Cout;
                float b0 = bias[col], b1 = bias[col+1];
                float c0 = cG[col],  c1 = cG[col+1];
                float r0 = rsG[row], r8 = rsG[row+8];
                *(float2*)(C + (long)row*ldc + col) =
                    make_float2(tanhf(r0*(a[0]+c0)+b0), tanhf(r0*(a[1]+c1)+b1));
                *(float2*)(C + (long)(row+8)*ldc + col) =
                    make_float2(tanhf(r8*(a[2]+c0)+b0), tanhf(r8*(a[3]+c1)+b1));
            }
        }
    }
}

// ---------------- rc[b,e] = 1 / sum of column partials ------------------------
__global__ void __launch_bounds__(256) rc_kernel(){
    int i = blockIdx.x*256 + threadIdx.x;       // 0..16383
    int b = i >> 12, e = i & (SS-1);
    const float* p = g_cpart + (long)b*32*SS + e;
    float s = 0.f;
    #pragma unroll
    for (int t = 0; t < 32; t++) s += p[(long)t*SS];
    g_rc[i] = 1.0f/s;
}

// ---------------- rowsum: rs[b,s] = sum_e E[b,s,e] * rc[b,e] ------------------
// one warp per row, uint4 (8-half) loads, float4 rc loads
__global__ void __launch_bounds__(256) rowsum_kernel(){
    __shared__ float rcs[SS];
    int b = blockIdx.y;
    for (int i = threadIdx.x; i < SS; i += 256) rcs[i] = g_rc[b*SS + i];
    __syncthreads();
    int lane = threadIdx.x & 31, warp = threadIdx.x >> 5;
    int r = blockIdx.x*8 + warp;
    const uint4* row = (const uint4*)(g_E + ((long)b*SS + r)*(long)SS);
    float s = 0.f;
    #pragma unroll
    for (int it = 0; it < 16; it++){
        int j = it*32 + lane;                    // uint4 index -> halfs [8j, 8j+8)
        uint4 v = row[j];
        const float4* c4 = (const float4*)(rcs + 8*j);
        float4 ca = c4[0], cb = c4[1];
        float2 f0 = __half22float2(*(const __half2*)&v.x);
        float2 f1 = __half22float2(*(const __half2*)&v.y);
        float2 f2 = __half22float2(*(const __half2*)&v.z);
        float2 f3 = __half22float2(*(const __half2*)&v.w);
        s += f0.x*ca.x + f0.y*ca.y + f1.x*ca.z + f1.y*ca.w
           + f2.x*cb.x + f2.y*cb.y + f3.x*cb.z + f3.y*cb.w;
    }
    #pragma unroll
    for (int o = 16; o; o >>= 1) s += __shfl_xor_sync(0xffffffffu, s, o);
    if (lane == 0) g_rs[b*SS + r] = s;
}

// ---------------- launch -----------------------------------------------------
extern "C" void kernel_launch(void* const* d_in, const int* in_sizes, int n_in,
                              void* d_out, int out_size)
{
    const float* xs = (const float*)d_in[0];
    const float* Wk = (const float*)d_in[1]; const float* bk = (const float*)d_in[2];
    const float* Wq = (const float*)d_in[3]; const float* bq = (const float*)d_in[4];
    const float* Wv = (const float*)d_in[5]; const float* bv = (const float*)d_in[6];
    const float* Wl = (const float*)d_in[7]; const float* bl = (const float*)d_in[8];

    void *p_xhi,*p_xlo,*p_KQ,*p_E,*p_bkq,*p_Wkq;
    void *p_Mhi,*p_Mlo,*p_rs,*p_c;
    cudaGetSymbolAddress(&p_xhi, g_xhi);   cudaGetSymbolAddress(&p_xlo, g_xlo);
    cudaGetSymbolAddress(&p_KQ,  g_KQ);    cudaGetSymbolAddress(&p_E,   g_E);
    cudaGetSymbolAddress(&p_bkq, g_bkq);   cudaGetSymbolAddress(&p_Wkq, g_Wkq);
    cudaGetSymbolAddress(&p_Mhi, g_Mhi);   cudaGetSymbolAddress(&p_Mlo, g_Mlo);
    cudaGetSymbolAddress(&p_rs,  g_rs);    cudaGetSymbolAddress(&p_c,   g_c);

    constexpr int AR = Bb_M*LDS;
    const size_t smemPlain = (size_t)2*AR*sizeof(__nv_bfloat16);   // 36864
    const size_t smemSplit = (size_t)4*AR*sizeof(__nv_bfloat16);   // 73728

    cudaFuncSetAttribute(gemm_kernel<4,true>,
                         cudaFuncAttributeMaxDynamicSharedMemorySize, (int)smemSplit);

    // 1. prep (x split, K|Q weight stack) + M = Wl@Wv split + c = Wl@bv
    prep_kernel<<<(BSD + 255)/256, 256>>>(xs, Wk, Wq, bk, bq);
    matM_kernel<<<dim3(DD/16, DD/16), dim3(16,16)>>>(Wl, Wv);
    cvec_kernel<<<DD/8, 256>>>(Wl, bv);

    // 2. merged K|Q projection -> g_KQ [16384, 1024]
    dim3 gkq(2*DD/Bb_N, (BB*SS)/Bb_M, 1);   // (8, 128)
    gemm_kernel<0,false><<<gkq, 256, smemPlain>>>(
        (const __nv_bfloat16*)p_xhi, nullptr, (const __nv_bfloat16*)p_Wkq, nullptr,
        (const float*)p_bkq, p_KQ, DD, DD, DD, 2*DD, 0, 0, 0, nullptr, nullptr);

    // 3. E = exp(K Q^T / 512) fp16 + fused fp16-rounded column partials
    dim3 gq(SS/Bb_N, SS/Bb_M, BB);          // (32, 32, 4)
    gemm_kernel<2,false><<<gq, 256, smemPlain>>>(
        (const __nv_bfloat16*)p_KQ, nullptr,
        (const __nv_bfloat16*)p_KQ + DD, nullptr,
        nullptr, p_E, DD, 2*DD, 2*DD, SS,
        (long)SS*2*DD, (long)SS*2*DD, (long)SS*SS, nullptr, nullptr);

    // 4. rc = 1/colsum; 5. rowsum (vectorized)
    rc_kernel<<<BB*SS/256, 256>>>();
    rowsum_kernel<<<dim3(SS/8, BB), 256>>>();

    // 6. out = tanh(rs*(x M^T + c) + bl)  — single fused split GEMM
    dim3 gp(DD/Bb_N, (BB*SS)/Bb_M, 1);      // (4, 128)
    gemm_kernel<4,true><<<gp, 256, smemSplit>>>(
        (const __nv_bfloat16*)p_xhi, (const __nv_bfloat16*)p_xlo,
        (const __nv_bfloat16*)p_Mhi, (const __nv_bfloat16*)p_Mlo,
        bl, d_out, DD, DD, DD, DD, 0, 0, 0,
        (const float*)p_rs, (const float*)p_c);
}

// round 9
// speedup vs baseline: 1.1403x; 1.0401x over previous
#include <cuda_runtime.h>
#include <cuda_bf16.h>
#include <cuda_fp16.h>
#include <cstdint>

#define BB 4
#define SS 4096
#define DD 512
#define BSD (BB*SS*DD)      // 8388608

// ---------------- device scratch (static; no allocations allowed) -------------
__device__ __nv_bfloat16 g_xhi[BSD];
__device__ __nv_bfloat16 g_xlo[BSD];
__device__ __nv_bfloat16 g_KQ[(size_t)BB*SS*2*DD];     // [16384, 1024] = K|Q
__device__ __half        g_E[(size_t)BB*SS*SS];        // 128MB
__device__ float         g_cpart[(size_t)BB*32*SS];    // per-row-tile column partials
__device__ float         g_rc[BB*SS];   // 1/colsum
__device__ float         g_rs[BB*SS];   // rowsum
__device__ __nv_bfloat16 g_Wkq[2*DD*DD];
__device__ float         g_bkq[2*DD];
__device__ __nv_bfloat16 g_Mhi[DD*DD], g_Mlo[DD*DD];   // M = Wl @ Wv, hi/lo split
__device__ float         g_c[DD];                      // c = Wl @ bv

// ---------------- helpers ----------------------------------------------------
__device__ __forceinline__ unsigned sptr(const void* p){
    return (unsigned)__cvta_generic_to_shared(p);
}
__device__ __forceinline__ void ldm4(unsigned r[4], unsigned addr){
    asm volatile("ldmatrix.sync.aligned.m8n8.x4.shared.b16 {%0,%1,%2,%3}, [%4];"
        : "=r"(r[0]),"=r"(r[1]),"=r"(r[2]),"=r"(r[3]) : "r"(addr));
}
__device__ __forceinline__ void mma16816(float c[4], const unsigned a[4], const unsigned b[2]){
    asm volatile("mma.sync.aligned.m16n8k16.row.col.f32.bf16.bf16.f32 "
        "{%0,%1,%2,%3},{%4,%5,%6,%7},{%8,%9},{%0,%1,%2,%3};"
        : "+f"(c[0]),"+f"(c[1]),"+f"(c[2]),"+f"(c[3])
        : "r"(a[0]),"r"(a[1]),"r"(a[2]),"r"(a[3]),"r"(b[0]),"r"(b[1]));
}

// ---------------- prep: x hi/lo split + KQ weight stack (vectorized) ----------
__global__ void prep_kernel(const float* __restrict__ xs, const float* __restrict__ Wk,
                            const float* __restrict__ Wq, const float* __restrict__ bk,
                            const float* __restrict__ bq){
    long idx = (long)blockIdx.x*blockDim.x + threadIdx.x;
    long i = idx*4;
    if (i < (long)BSD){
        float4 v = *(const float4*)(xs + i);
        __nv_bfloat16 h0=__float2bfloat16(v.x), h1=__float2bfloat16(v.y),
                      h2=__float2bfloat16(v.z), h3=__float2bfloat16(v.w);
        __nv_bfloat162 p0; p0.x=h0; p0.y=h1;
        __nv_bfloat162 p1; p1.x=h2; p1.y=h3;
        *(__nv_bfloat162*)(g_xhi + i)     = p0;
        *(__nv_bfloat162*)(g_xhi + i + 2) = p1;
        __nv_bfloat162 q0, q1;
        q0.x = __float2bfloat16(v.x - __bfloat162float(h0));
        q0.y = __float2bfloat16(v.y - __bfloat162float(h1));
        q1.x = __float2bfloat16(v.z - __bfloat162float(h2));
        q1.y = __float2bfloat16(v.w - __bfloat162float(h3));
        *(__nv_bfloat162*)(g_xlo + i)     = q0;
        *(__nv_bfloat162*)(g_xlo + i + 2) = q1;
    }
    if (i < DD*DD){
        float4 a = *(const float4*)(Wk + i);
        float4 b = *(const float4*)(Wq + i);
        __nv_bfloat162 ka; ka.x=__float2bfloat16(a.x); ka.y=__float2bfloat16(a.y);
        __nv_bfloat162 kb; kb.x=__float2bfloat16(a.z); kb.y=__float2bfloat16(a.w);
        __nv_bfloat162 qa; qa.x=__float2bfloat16(b.x); qa.y=__float2bfloat16(b.y);
        __nv_bfloat162 qb; qb.x=__float2bfloat16(b.z); qb.y=__float2bfloat16(b.w);
        *(__nv_bfloat162*)(g_Wkq + i)            = ka;
        *(__nv_bfloat162*)(g_Wkq + i + 2)        = kb;
        *(__nv_bfloat162*)(g_Wkq + DD*DD + i)    = qa;
        *(__nv_bfloat162*)(g_Wkq + DD*DD + i + 2)= qb;
    }
    if (idx < DD){
        g_bkq[idx] = bk[idx]; g_bkq[DD + idx] = bq[idx];
    }
}

// ---------------- M = Wl @ Wv (fp32 tiled) -> hi/lo bf16 split ----------------
__global__ void matM_kernel(const float* __restrict__ Wl, const float* __restrict__ Wv){
    __shared__ float sA[16][16], sB[16][17];
    int tx = threadIdx.x, ty = threadIdx.y;
    int e = blockIdx.y*16 + ty, d = blockIdx.x*16 + tx;
    float acc = 0.f;
    for (int t0 = 0; t0 < DD; t0 += 16){
        sA[ty][tx] = Wl[e*DD + t0 + tx];
        sB[ty][tx] = Wv[(t0 + ty)*DD + d];
        __syncthreads();
        #pragma unroll
        for (int t = 0; t < 16; t++) acc += sA[ty][t]*sB[t][tx];
        __syncthreads();
    }
    __nv_bfloat16 h = __float2bfloat16(acc);
    g_Mhi[e*DD + d] = h;
    g_Mlo[e*DD + d] = __float2bfloat16(acc - __bfloat162float(h));
}

// ---------------- c = Wl @ bv (one warp per output) ---------------------------
__global__ void cvec_kernel(const float* __restrict__ Wl, const float* __restrict__ bv){
    int e = blockIdx.x*8 + (threadIdx.x >> 5), lane = threadIdx.x & 31;
    float s = 0.f;
    for (int d = lane; d < DD; d += 32) s += Wl[e*DD + d]*bv[d];
    #pragma unroll
    for (int o = 16; o; o >>= 1) s += __shfl_xor_sync(0xffffffffu, s, o);
    if (lane == 0) g_c[e] = s;
}

// ---------------- generic C = A * B^T GEMM ------------------------------------
// EPI: 0 bf16+bias (K|Q proj)
//      2 exp->fp16 E + fp16-rounded column partials (QK)
//      4 tanh(rs*(acc + c) + bias) -> fp32 (final fused output)
// SPLIT: 3-product hi/lo accumulation.  KT: K-tile, LDSx: smem row stride.
constexpr int Bb_M = 128, Bb_N = 128;

template<int EPI, bool SPLIT, int KT, int LDSx>
__global__ void __launch_bounds__(256)
gemm_kernel(const __nv_bfloat16* __restrict__ A, const __nv_bfloat16* __restrict__ A2,
            const __nv_bfloat16* __restrict__ B, const __nv_bfloat16* __restrict__ B2,
            const float* __restrict__ bias, void* __restrict__ Cout,
            int Kd, int lda, int ldb, int ldc,
            long batchA, long batchB, long batchC,
            const float* __restrict__ rsG, const float* __restrict__ cG)
{
    extern __shared__ __nv_bfloat16 sm[];
    constexpr int AR = Bb_M*LDSx;
    __nv_bfloat16* As  = sm;
    __nv_bfloat16* Bs  = sm + AR;
    __nv_bfloat16* As2 = SPLIT ? sm + 2*AR : nullptr;
    __nv_bfloat16* Bs2 = SPLIT ? sm + 3*AR : nullptr;

    int z = blockIdx.z;
    const __nv_bfloat16* Ag  = A + z*batchA;
    const __nv_bfloat16* Bg  = B + z*batchB;
    const __nv_bfloat16* A2g = SPLIT ? A2 + z*batchA : nullptr;
    const __nv_bfloat16* B2g = SPLIT ? B2 + z*batchB : nullptr;

    int tid = threadIdx.x, lane = tid & 31, warp = tid >> 5;
    int wm = warp >> 2, wn = warp & 3;           // 2x4 warp grid -> 64x32 per warp
    int bm0 = blockIdx.y * Bb_M, bn0 = blockIdx.x * Bb_N;
    int lr = tid >> 1;                            // loader row 0..127
    int lc = (tid & 1) * 8;                       // loader col base (halfs)

    float acc[4][4][4] = {};

    for (int k0 = 0; k0 < Kd; k0 += KT){
        {
            const __nv_bfloat16* a = Ag + (long)(bm0+lr)*lda + k0 + lc;
            __nv_bfloat16* da = As + lr*LDSx + lc;
            const __nv_bfloat16* b = Bg + (long)(bn0+lr)*ldb + k0 + lc;
            __nv_bfloat16* db = Bs + lr*LDSx + lc;
            #pragma unroll
            for (int q = 0; q < KT/16; q++){
                *(uint4*)(da + q*16) = *(const uint4*)(a + q*16);
                *(uint4*)(db + q*16) = *(const uint4*)(b + q*16);
            }
            if (SPLIT){
                const __nv_bfloat16* a2 = A2g + (long)(bm0+lr)*lda + k0 + lc;
                __nv_bfloat16* da2 = As2 + lr*LDSx + lc;
                const __nv_bfloat16* b2 = B2g + (long)(bn0+lr)*ldb + k0 + lc;
                __nv_bfloat16* db2 = Bs2 + lr*LDSx + lc;
                #pragma unroll
                for (int q = 0; q < KT/16; q++){
                    *(uint4*)(da2 + q*16) = *(const uint4*)(a2 + q*16);
                    *(uint4*)(db2 + q*16) = *(const uint4*)(b2 + q*16);
                }
            }
        }
        __syncthreads();

        #pragma unroll
        for (int kk = 0; kk < KT; kk += 16){
            unsigned af[4][4], bf[4][2];
            unsigned af2[4][4], bf2[4][2];
            int arow = wm*64 + (lane & 15);
            int acol = kk + 8*(lane >> 4);
            #pragma unroll
            for (int mi=0; mi<4; mi++){
                ldm4(af[mi],  sptr(As  + (arow + mi*16)*LDSx + acol));
                if (SPLIT) ldm4(af2[mi], sptr(As2 + (arow + mi*16)*LDSx + acol));
            }
            int brow = wn*32 + (lane & 7) + ((lane & 16) ? 8 : 0);
            int bcol = kk + ((lane & 8) ? 8 : 0);
            #pragma unroll
            for (int nb=0; nb<2; nb++){
                unsigned tmp[4];
                ldm4(tmp, sptr(Bs + (brow + nb*16)*LDSx + bcol));
                bf[2*nb][0]=tmp[0]; bf[2*nb][1]=tmp[1];
                bf[2*nb+1][0]=tmp[2]; bf[2*nb+1][1]=tmp[3];
                if (SPLIT){
                    ldm4(tmp, sptr(Bs2 + (brow + nb*16)*LDSx + bcol));
                    bf2[2*nb][0]=tmp[0]; bf2[2*nb][1]=tmp[1];
                    bf2[2*nb+1][0]=tmp[2]; bf2[2*nb+1][1]=tmp[3];
                }
            }
            #pragma unroll
            for (int mi=0; mi<4; mi++)
                #pragma unroll
                for (int ni=0; ni<4; ni++){
                    mma16816(acc[mi][ni], af[mi], bf[ni]);
                    if (SPLIT){
                        mma16816(acc[mi][ni], af[mi],  bf2[ni]);
                        mma16816(acc[mi][ni], af2[mi], bf[ni]);
                    }
                }
        }
        __syncthreads();
    }

    // ---------------- epilogue ----------------
    int tr = lane >> 2, tc = (lane & 3) * 2;
    if (EPI == 2){
        __half* C = (__half*)Cout + z*batchC;
        const float inv = 1.0f/512.0f;
        float csum[4][2];
        #pragma unroll
        for (int ni=0; ni<4; ni++){ csum[ni][0]=0.f; csum[ni][1]=0.f; }
        #pragma unroll
        for (int mi=0; mi<4; mi++){
            #pragma unroll
            for (int ni=0; ni<4; ni++){
                int row = bm0 + wm*64 + mi*16 + tr;
                int col = bn0 + wn*32 + ni*8 + tc;
                float* a = acc[mi][ni];
                // round to fp16 FIRST, then sum the rounded value -> colsum and
                // rowsum see identical quantization (error cancels in the ratio)
                __half h0 = __float2half_rn(__expf(a[0]*inv));
                __half h1 = __float2half_rn(__expf(a[1]*inv));
                __half h2 = __float2half_rn(__expf(a[2]*inv));
                __half h3 = __float2half_rn(__expf(a[3]*inv));
                *(__half2*)(C + (long)row*ldc + col)     = __halves2half2(h0, h1);
                *(__half2*)(C + (long)(row+8)*ldc + col) = __halves2half2(h2, h3);
                csum[ni][0] += __half2float(h0) + __half2float(h2);
                csum[ni][1] += __half2float(h1) + __half2float(h3);
            }
        }
        #pragma unroll
        for (int ni=0; ni<4; ni++)
            #pragma unroll
            for (int j=0; j<2; j++){
                float s = csum[ni][j];
                s += __shfl_xor_sync(0xffffffffu, s, 4);
                s += __shfl_xor_sync(0xffffffffu, s, 8);
                s += __shfl_xor_sync(0xffffffffu, s, 16);
                csum[ni][j] = s;
            }
        float* cps = (float*)sm;   // smem reuse: all compute done (sync at loop end)
        if (lane < 4){
            #pragma unroll
            for (int ni=0; ni<4; ni++){
                cps[wm*128 + wn*32 + ni*8 + tc]     = csum[ni][0];
                cps[wm*128 + wn*32 + ni*8 + tc + 1] = csum[ni][1];
            }
        }
        __syncthreads();
        if (tid < 128)
            g_cpart[((long)z*32 + blockIdx.y)*SS + bn0 + tid] = cps[tid] + cps[128 + tid];
        return;
    }
    #pragma unroll
    for (int mi=0; mi<4; mi++){
        #pragma unroll
        for (int ni=0; ni<4; ni++){
            int row = bm0 + wm*64 + mi*16 + tr;
            int col = bn0 + wn*32 + ni*8 + tc;
            float* a = acc[mi][ni];
            if (EPI == 0){
                __nv_bfloat16* C = (__nv_bfloat16*)Cout;
                float b0 = bias[col], b1 = bias[col+1];
                *(__nv_bfloat162*)(C + (long)row*ldc + col)     = __floats2bfloat162_rn(a[0]+b0, a[1]+b1);
                *(__nv_bfloat162*)(C + (long)(row+8)*ldc + col) = __floats2bfloat162_rn(a[2]+b0, a[3]+b1);
            } else {  // EPI == 4: out = tanh(rs*(acc + c) + bl)
                float* C = (float*)Cout;
                float b0 = bias[col], b1 = bias[col+1];
                float c0 = cG[col],  c1 = cG[col+1];
                float r0 = rsG[row], r8 = rsG[row+8];
                *(float2*)(C + (long)row*ldc + col) =
                    make_float2(tanhf(r0*(a[0]+c0)+b0), tanhf(r0*(a[1]+c1)+b1));
                *(float2*)(C + (long)(row+8)*ldc + col) =
                    make_float2(tanhf(r8*(a[2]+c0)+b0), tanhf(r8*(a[3]+c1)+b1));
            }
        }
    }
}

// ---------------- rc[b,e] = 1 / sum of column partials ------------------------
__global__ void __launch_bounds__(256) rc_kernel(){
    int i = blockIdx.x*256 + threadIdx.x;       // 0..16383
    int b = i >> 12, e = i & (SS-1);
    const float* p = g_cpart + (long)b*32*SS + e;
    float s = 0.f;
    #pragma unroll
    for (int t = 0; t < 32; t++) s += p[(long)t*SS];
    g_rc[i] = 1.0f/s;
}

// ---------------- rowsum: rs[b,s] = sum_e E[b,s,e] * rc[b,e] ------------------
// one warp per row, uint4 (8-half) loads, float4 rc loads
__global__ void __launch_bounds__(256) rowsum_kernel(){
    __shared__ float rcs[SS];
    int b = blockIdx.y;
    for (int i = threadIdx.x; i < SS; i += 256) rcs[i] = g_rc[b*SS + i];
    __syncthreads();
    int lane = threadIdx.x & 31, warp = threadIdx.x >> 5;
    int r = blockIdx.x*8 + warp;
    const uint4* row = (const uint4*)(g_E + ((long)b*SS + r)*(long)SS);
    float s = 0.f;
    #pragma unroll
    for (int it = 0; it < 16; it++){
        int j = it*32 + lane;                    // uint4 index -> halfs [8j, 8j+8)
        uint4 v = row[j];
        const float4* c4 = (const float4*)(rcs + 8*j);
        float4 ca = c4[0], cb = c4[1];
        float2 f0 = __half22float2(*(const __half2*)&v.x);
        float2 f1 = __half22float2(*(const __half2*)&v.y);
        float2 f2 = __half22float2(*(const __half2*)&v.z);
        float2 f3 = __half22float2(*(const __half2*)&v.w);
        s += f0.x*ca.x + f0.y*ca.y + f1.x*ca.z + f1.y*ca.w
           + f2.x*cb.x + f2.y*cb.y + f3.x*cb.z + f3.y*cb.w;
    }
    #pragma unroll
    for (int o = 16; o; o >>= 1) s += __shfl_xor_sync(0xffffffffu, s, o);
    if (lane == 0) g_rs[b*SS + r] = s;
}

// ---------------- launch -----------------------------------------------------
extern "C" void kernel_launch(void* const* d_in, const int* in_sizes, int n_in,
                              void* d_out, int out_size)
{
    const float* xs = (const float*)d_in[0];
    const float* Wk = (const float*)d_in[1]; const float* bk = (const float*)d_in[2];
    const float* Wq = (const float*)d_in[3]; const float* bq = (const float*)d_in[4];
    const float* Wv = (const float*)d_in[5]; const float* bv = (const float*)d_in[6];
    const float* Wl = (const float*)d_in[7]; const float* bl = (const float*)d_in[8];

    void *p_xhi,*p_xlo,*p_KQ,*p_E,*p_bkq,*p_Wkq;
    void *p_Mhi,*p_Mlo,*p_rs,*p_c;
    cudaGetSymbolAddress(&p_xhi, g_xhi);   cudaGetSymbolAddress(&p_xlo, g_xlo);
    cudaGetSymbolAddress(&p_KQ,  g_KQ);    cudaGetSymbolAddress(&p_E,   g_E);
    cudaGetSymbolAddress(&p_bkq, g_bkq);   cudaGetSymbolAddress(&p_Wkq, g_Wkq);
    cudaGetSymbolAddress(&p_Mhi, g_Mhi);   cudaGetSymbolAddress(&p_Mlo, g_Mlo);
    cudaGetSymbolAddress(&p_rs,  g_rs);    cudaGetSymbolAddress(&p_c,   g_c);

    constexpr int KT_P = 128, LDS_P = 136;   // plain kernels
    constexpr int KT_S = 64,  LDS_S = 72;    // split kernel
    const size_t smemPlain = (size_t)2*Bb_M*LDS_P*sizeof(__nv_bfloat16);  // 69632
    const size_t smemSplit = (size_t)4*Bb_M*LDS_S*sizeof(__nv_bfloat16);  // 73728

    cudaFuncSetAttribute((const void*)gemm_kernel<0,false,KT_P,LDS_P>,
                         cudaFuncAttributeMaxDynamicSharedMemorySize, (int)smemPlain);
    cudaFuncSetAttribute((const void*)gemm_kernel<2,false,KT_P,LDS_P>,
                         cudaFuncAttributeMaxDynamicSharedMemorySize, (int)smemPlain);
    cudaFuncSetAttribute((const void*)gemm_kernel<4,true,KT_S,LDS_S>,
                         cudaFuncAttributeMaxDynamicSharedMemorySize, (int)smemSplit);

    // 1. prep (vectorized) + M = Wl@Wv split + c = Wl@bv
    prep_kernel<<<(BSD/4 + 255)/256, 256>>>(xs, Wk, Wq, bk, bq);
    matM_kernel<<<dim3(DD/16, DD/16), dim3(16,16)>>>(Wl, Wv);
    cvec_kernel<<<DD/8, 256>>>(Wl, bv);

    // 2. merged K|Q projection -> g_KQ [16384, 1024]
    dim3 gkq(2*DD/Bb_N, (BB*SS)/Bb_M, 1);   // (8, 128)
    gemm_kernel<0,false,KT_P,LDS_P><<<gkq, 256, smemPlain>>>(
        (const __nv_bfloat16*)p_xhi, nullptr, (const __nv_bfloat16*)p_Wkq, nullptr,
        (const float*)p_bkq, p_KQ, DD, DD, DD, 2*DD, 0, 0, 0, nullptr, nullptr);

    // 3. E = exp(K Q^T / 512) fp16 + fused fp16-rounded column partials
    dim3 gq(SS/Bb_N, SS/Bb_M, BB);          // (32, 32, 4)
    gemm_kernel<2,false,KT_P,LDS_P><<<gq, 256, smemPlain>>>(
        (const __nv_bfloat16*)p_KQ, nullptr,
        (const __nv_bfloat16*)p_KQ + DD, nullptr,
        nullptr, p_E, DD, 2*DD, 2*DD, SS,
        (long)SS*2*DD, (long)SS*2*DD, (long)SS*SS, nullptr, nullptr);

    // 4. rc = 1/colsum; 5. rowsum (vectorized)
    rc_kernel<<<BB*SS/256, 256>>>();
    rowsum_kernel<<<dim3(SS/8, BB), 256>>>();

    // 6. out = tanh(rs*(x M^T + c) + bl)  — single fused split GEMM
    dim3 gp(DD/Bb_N, (BB*SS)/Bb_M, 1);      // (4, 128)
    gemm_kernel<4,true,KT_S,LDS_S><<<gp, 256, smemSplit>>>(
        (const __nv_bfloat16*)p_xhi, (const __nv_bfloat16*)p_xlo,
        (const __nv_bfloat16*)p_Mhi, (const __nv_bfloat16*)p_Mlo,
        bl, d_out, DD, DD, DD, DD, 0, 0, 0,
        (const float*)p_rs, (const float*)p_c);
}

// round 11
// speedup vs baseline: 1.1789x; 1.0338x over previous
#include <cuda_runtime.h>
#include <cuda_bf16.h>
#include <cuda_fp16.h>
#include <cstdint>

#define BB 4
#define SS 4096
#define DD 512
#define BSD (BB*SS*DD)      // 8388608

// ---------------- device scratch (static; no allocations allowed) -------------
__device__ __nv_bfloat16 g_xhi[BSD];
__device__ __nv_bfloat16 g_xlo[BSD];
__device__ __nv_bfloat16 g_KQ[(size_t)BB*SS*2*DD];     // [16384, 1024] = K|Q
__device__ __half        g_E[(size_t)BB*SS*SS];        // 128MB
__device__ float         g_cpart[(size_t)BB*32*SS];    // per-row-tile column partials
__device__ float         g_rc[BB*SS];   // 1/colsum
__device__ float         g_rs[BB*SS];   // rowsum
__device__ __nv_bfloat16 g_Wkq[2*DD*DD];
__device__ float         g_bkq[2*DD];
__device__ __nv_bfloat16 g_Mhi[DD*DD], g_Mlo[DD*DD];   // M = Wl @ Wv, hi/lo split
__device__ float         g_c[DD];                      // c = Wl @ bv

// ---------------- helpers ----------------------------------------------------
__device__ __forceinline__ unsigned sptr(const void* p){
    return (unsigned)__cvta_generic_to_shared(p);
}
__device__ __forceinline__ void cp16(unsigned saddr, const void* gmem){
    asm volatile("cp.async.cg.shared.global [%0], [%1], 16;"
        :: "r"(saddr), "l"(gmem));
}
__device__ __forceinline__ void ldm4(unsigned r[4], unsigned addr){
    asm volatile("ldmatrix.sync.aligned.m8n8.x4.shared.b16 {%0,%1,%2,%3}, [%4];"
        : "=r"(r[0]),"=r"(r[1]),"=r"(r[2]),"=r"(r[3]) : "r"(addr));
}
__device__ __forceinline__ void mma16816(float c[4], const unsigned a[4], const unsigned b[2]){
    asm volatile("mma.sync.aligned.m16n8k16.row.col.f32.bf16.bf16.f32 "
        "{%0,%1,%2,%3},{%4,%5,%6,%7},{%8,%9},{%0,%1,%2,%3};"
        : "+f"(c[0]),"+f"(c[1]),"+f"(c[2]),"+f"(c[3])
        : "r"(a[0]),"r"(a[1]),"r"(a[2]),"r"(a[3]),"r"(b[0]),"r"(b[1]));
}

// ---------------- prep: x hi/lo split + KQ weight stack (vectorized) ----------
__global__ void prep_kernel(const float* __restrict__ xs, const float* __restrict__ Wk,
                            const float* __restrict__ Wq, const float* __restrict__ bk,
                            const float* __restrict__ bq){
    long idx = (long)blockIdx.x*blockDim.x + threadIdx.x;
    long i = idx*4;
    if (i < (long)BSD){
        float4 v = *(const float4*)(xs + i);
        __nv_bfloat16 h0=__float2bfloat16(v.x), h1=__float2bfloat16(v.y),
                      h2=__float2bfloat16(v.z), h3=__float2bfloat16(v.w);
        __nv_bfloat162 p0; p0.x=h0; p0.y=h1;
        __nv_bfloat162 p1; p1.x=h2; p1.y=h3;
        *(__nv_bfloat162*)(g_xhi + i)     = p0;
        *(__nv_bfloat162*)(g_xhi + i + 2) = p1;
        __nv_bfloat162 q0, q1;
        q0.x = __float2bfloat16(v.x - __bfloat162float(h0));
        q0.y = __float2bfloat16(v.y - __bfloat162float(h1));
        q1.x = __float2bfloat16(v.z - __bfloat162float(h2));
        q1.y = __float2bfloat16(v.w - __bfloat162float(h3));
        *(__nv_bfloat162*)(g_xlo + i)     = q0;
        *(__nv_bfloat162*)(g_xlo + i + 2) = q1;
    }
    if (i < DD*DD){
        float4 a = *(const float4*)(Wk + i);
        float4 b = *(const float4*)(Wq + i);
        __nv_bfloat162 ka; ka.x=__float2bfloat16(a.x); ka.y=__float2bfloat16(a.y);
        __nv_bfloat162 kb; kb.x=__float2bfloat16(a.z); kb.y=__float2bfloat16(a.w);
        __nv_bfloat162 qa; qa.x=__float2bfloat16(b.x); qa.y=__float2bfloat16(b.y);
        __nv_bfloat162 qb; qb.x=__float2bfloat16(b.z); qb.y=__float2bfloat16(b.w);
        *(__nv_bfloat162*)(g_Wkq + i)            = ka;
        *(__nv_bfloat162*)(g_Wkq + i + 2)        = kb;
        *(__nv_bfloat162*)(g_Wkq + DD*DD + i)    = qa;
        *(__nv_bfloat162*)(g_Wkq + DD*DD + i + 2)= qb;
    }
    if (idx < DD){
        g_bkq[idx] = bk[idx]; g_bkq[DD + idx] = bq[idx];
    }
}

// ---------------- M = Wl @ Wv (fp32 tiled) -> hi/lo bf16 split ----------------
__global__ void matM_kernel(const float* __restrict__ Wl, const float* __restrict__ Wv){
    __shared__ float sA[16][16], sB[16][17];
    int tx = threadIdx.x, ty = threadIdx.y;
    int e = blockIdx.y*16 + ty, d = blockIdx.x*16 + tx;
    float acc = 0.f;
    for (int t0 = 0; t0 < DD; t0 += 16){
        sA[ty][tx] = Wl[e*DD + t0 + tx];
        sB[ty][tx] = Wv[(t0 + ty)*DD + d];
        __syncthreads();
        #pragma unroll
        for (int t = 0; t < 16; t++) acc += sA[ty][t]*sB[t][tx];
        __syncthreads();
    }
    __nv_bfloat16 h = __float2bfloat16(acc);
    g_Mhi[e*DD + d] = h;
    g_Mlo[e*DD + d] = __float2bfloat16(acc - __bfloat162float(h));
}

// ---------------- c = Wl @ bv (one warp per output) ---------------------------
__global__ void cvec_kernel(const float* __restrict__ Wl, const float* __restrict__ bv){
    int e = blockIdx.x*8 + (threadIdx.x >> 5), lane = threadIdx.x & 31;
    float s = 0.f;
    for (int d = lane; d < DD; d += 32) s += Wl[e*DD + d]*bv[d];
    #pragma unroll
    for (int o = 16; o; o >>= 1) s += __shfl_xor_sync(0xffffffffu, s, o);
    if (lane == 0) g_c[e] = s;
}

constexpr int Bb_M = 128, Bb_N = 128;

// ================== PIPELINED plain GEMM (cp.async 2-stage) ===================
// C = A * B^T.  EPI: 0 bf16+bias | 2 exp->fp16 E + fp16-rounded column partials
constexpr int KT_P = 64, LDS_P = 72;

template<int EPI>
__global__ void __launch_bounds__(256)
gemm_pipe(const __nv_bfloat16* __restrict__ A, const __nv_bfloat16* __restrict__ B,
          const float* __restrict__ bias, void* __restrict__ Cout,
          int Kd, int lda, int ldb, int ldc,
          long batchA, long batchB, long batchC)
{
    extern __shared__ __nv_bfloat16 sm[];
    constexpr int AR = Bb_M*LDS_P;                 // halfs per buffer
    unsigned smb = sptr(sm);

    int z = blockIdx.z;
    const __nv_bfloat16* Ag = A + z*batchA;
    const __nv_bfloat16* Bg = B + z*batchB;

    int tid = threadIdx.x, lane = tid & 31, warp = tid >> 5;
    int wm = warp >> 2, wn = warp & 3;             // 2x4 -> 64x32 per warp
    int bm0 = blockIdx.y * Bb_M, bn0 = blockIdx.x * Bb_N;
    int lr = tid >> 1;                              // loader row 0..127
    int lc = (tid & 1) * 8;                         // loader col base (halfs)

    const __nv_bfloat16* aP = Ag + (long)(bm0+lr)*lda + lc;
    const __nv_bfloat16* bP = Bg + (long)(bn0+lr)*ldb + lc;
    unsigned daB = smb + (unsigned)(lr*LDS_P + lc)*2;  // byte addr in stage 0 A

    float acc[4][4][4] = {};

    auto fill = [&](int k0, int s){
        unsigned da = daB + (unsigned)(s*2*AR)*2;
        unsigned db = da + (unsigned)AR*2;
        const __nv_bfloat16* a = aP + k0;
        const __nv_bfloat16* b = bP + k0;
        #pragma unroll
        for (int q = 0; q < KT_P/16; q++){
            cp16(da + q*32, a + q*16);
            cp16(db + q*32, b + q*16);
        }
    };

    int n = Kd / KT_P;
    fill(0, 0);
    asm volatile("cp.async.commit_group;");

    for (int it = 0; it < n; ++it){
        int cur = it & 1;
        if (it + 1 < n) fill((it+1)*KT_P, cur ^ 1);
        asm volatile("cp.async.commit_group;");
        if (it + 1 < n) asm volatile("cp.async.wait_group 1;");
        else            asm volatile("cp.async.wait_group 0;");
        __syncthreads();

        __nv_bfloat16* As = sm + cur*2*AR;
        __nv_bfloat16* Bs = As + AR;
        #pragma unroll
        for (int kk = 0; kk < KT_P; kk += 16){
            unsigned af[4][4], bf[4][2];
            int arow = wm*64 + (lane & 15);
            int acol = kk + 8*(lane >> 4);
            #pragma unroll
            for (int mi=0; mi<4; mi++)
                ldm4(af[mi], sptr(As + (arow + mi*16)*LDS_P + acol));
            int brow = wn*32 + (lane & 7) + ((lane & 16) ? 8 : 0);
            int bcol = kk + ((lane & 8) ? 8 : 0);
            #pragma unroll
            for (int nb=0; nb<2; nb++){
                unsigned tmp[4];
                ldm4(tmp, sptr(Bs + (brow + nb*16)*LDS_P + bcol));
                bf[2*nb][0]=tmp[0]; bf[2*nb][1]=tmp[1];
                bf[2*nb+1][0]=tmp[2]; bf[2*nb+1][1]=tmp[3];
            }
            #pragma unroll
            for (int mi=0; mi<4; mi++)
                #pragma unroll
                for (int ni=0; ni<4; ni++)
                    mma16816(acc[mi][ni], af[mi], bf[ni]);
        }
        __syncthreads();   // all warps done reading before buffer is refilled
    }

    // ---------------- epilogue ----------------
    int tr = lane >> 2, tc = (lane & 3) * 2;
    if (EPI == 2){
        __half* C = (__half*)Cout + z*batchC;
        const float inv = 1.0f/512.0f;
        float csum[4][2];
        #pragma unroll
        for (int ni=0; ni<4; ni++){ csum[ni][0]=0.f; csum[ni][1]=0.f; }
        #pragma unroll
        for (int mi=0; mi<4; mi++){
            #pragma unroll
            for (int ni=0; ni<4; ni++){
                int row = bm0 + wm*64 + mi*16 + tr;
                int col = bn0 + wn*32 + ni*8 + tc;
                float* a = acc[mi][ni];
                // round to fp16 FIRST, then sum the rounded value -> colsum and
                // rowsum see identical quantization (error cancels in the ratio)
                __half h0 = __float2half_rn(__expf(a[0]*inv));
                __half h1 = __float2half_rn(__expf(a[1]*inv));
                __half h2 = __float2half_rn(__expf(a[2]*inv));
                __half h3 = __float2half_rn(__expf(a[3]*inv));
                *(__half2*)(C + (long)row*ldc + col)     = __halves2half2(h0, h1);
                *(__half2*)(C + (long)(row+8)*ldc + col) = __halves2half2(h2, h3);
                csum[ni][0] += __half2float(h0) + __half2float(h2);
                csum[ni][1] += __half2float(h1) + __half2float(h3);
            }
        }
        #pragma unroll
        for (int ni=0; ni<4; ni++)
            #pragma unroll
            for (int j=0; j<2; j++){
                float s = csum[ni][j];
                s += __shfl_xor_sync(0xffffffffu, s, 4);
                s += __shfl_xor_sync(0xffffffffu, s, 8);
                s += __shfl_xor_sync(0xffffffffu, s, 16);
                csum[ni][j] = s;
            }
        float* cps = (float*)sm;   // smem reuse: all compute done (sync at loop end)
        if (lane < 4){
            #pragma unroll
            for (int ni=0; ni<4; ni++){
                cps[wm*128 + wn*32 + ni*8 + tc]     = csum[ni][0];
                cps[wm*128 + wn*32 + ni*8 + tc + 1] = csum[ni][1];
            }
        }
        __syncthreads();
        if (tid < 128)
            g_cpart[((long)z*32 + blockIdx.y)*SS + bn0 + tid] = cps[tid] + cps[128 + tid];
        return;
    }
    #pragma unroll
    for (int mi=0; mi<4; mi++){
        #pragma unroll
        for (int ni=0; ni<4; ni++){
            int row = bm0 + wm*64 + mi*16 + tr;
            int col = bn0 + wn*32 + ni*8 + tc;
            float* a = acc[mi][ni];
            __nv_bfloat16* C = (__nv_bfloat16*)Cout;
            float b0 = bias[col], b1 = bias[col+1];
            *(__nv_bfloat162*)(C + (long)row*ldc + col)     = __floats2bfloat162_rn(a[0]+b0, a[1]+b1);
            *(__nv_bfloat162*)(C + (long)(row+8)*ldc + col) = __floats2bfloat162_rn(a[2]+b0, a[3]+b1);
        }
    }
}

// ================== split GEMM (round-9 proven, unchanged) ====================
// EPI 4: tanh(rs*(acc + c) + bias) -> fp32
constexpr int KT_S = 64, LDS_S = 72;

__global__ void __launch_bounds__(256)
gemm_split(const __nv_bfloat16* __restrict__ A, const __nv_bfloat16* __restrict__ A2,
           const __nv_bfloat16* __restrict__ B, const __nv_bfloat16* __restrict__ B2,
           const float* __restrict__ bias, float* __restrict__ Cout,
           const float* __restrict__ rsG, const float* __restrict__ cG)
{
    extern __shared__ __nv_bfloat16 sm[];
    constexpr int AR = Bb_M*LDS_S;
    __nv_bfloat16* As  = sm;
    __nv_bfloat16* Bs  = sm + AR;
    __nv_bfloat16* As2 = sm + 2*AR;
    __nv_bfloat16* Bs2 = sm + 3*AR;

    int tid = threadIdx.x, lane = tid & 31, warp = tid >> 5;
    int wm = warp >> 2, wn = warp & 3;
    int bm0 = blockIdx.y * Bb_M, bn0 = blockIdx.x * Bb_N;
    int lr = tid >> 1;
    int lc = (tid & 1) * 8;

    float acc[4][4][4] = {};

    for (int k0 = 0; k0 < DD; k0 += KT_S){
        {
            const __nv_bfloat16* a  = A  + (long)(bm0+lr)*DD + k0 + lc;
            const __nv_bfloat16* a2 = A2 + (long)(bm0+lr)*DD + k0 + lc;
            const __nv_bfloat16* b  = B  + (long)(bn0+lr)*DD + k0 + lc;
            const __nv_bfloat16* b2 = B2 + (long)(bn0+lr)*DD + k0 + lc;
            __nv_bfloat16* da  = As  + lr*LDS_S + lc;
            __nv_bfloat16* da2 = As2 + lr*LDS_S + lc;
            __nv_bfloat16* db  = Bs  + lr*LDS_S + lc;
            __nv_bfloat16* db2 = Bs2 + lr*LDS_S + lc;
            #pragma unroll
            for (int q = 0; q < KT_S/16; q++){
                *(uint4*)(da  + q*16) = *(const uint4*)(a  + q*16);
                *(uint4*)(db  + q*16) = *(const uint4*)(b  + q*16);
                *(uint4*)(da2 + q*16) = *(const uint4*)(a2 + q*16);
                *(uint4*)(db2 + q*16) = *(const uint4*)(b2 + q*16);
            }
        }
        __syncthreads();

        #pragma unroll
        for (int kk = 0; kk < KT_S; kk += 16){
            unsigned af[4][4], bf[4][2];
            unsigned af2[4][4], bf2[4][2];
            int arow = wm*64 + (lane & 15);
            int acol = kk + 8*(lane >> 4);
            #pragma unroll
            for (int mi=0; mi<4; mi++){
                ldm4(af[mi],  sptr(As  + (arow + mi*16)*LDS_S + acol));
                ldm4(af2[mi], sptr(As2 + (arow + mi*16)*LDS_S + acol));
            }
            int brow = wn*32 + (lane & 7) + ((lane & 16) ? 8 : 0);
            int bcol = kk + ((lane & 8) ? 8 : 0);
            #pragma unroll
            for (int nb=0; nb<2; nb++){
                unsigned tmp[4];
                ldm4(tmp, sptr(Bs + (brow + nb*16)*LDS_S + bcol));
                bf[2*nb][0]=tmp[0]; bf[2*nb][1]=tmp[1];
                bf[2*nb+1][0]=tmp[2]; bf[2*nb+1][1]=tmp[3];
                ldm4(tmp, sptr(Bs2 + (brow + nb*16)*LDS_S + bcol));
                bf2[2*nb][0]=tmp[0]; bf2[2*nb][1]=tmp[1];
                bf2[2*nb+1][0]=tmp[2]; bf2[2*nb+1][1]=tmp[3];
            }
            #pragma unroll
            for (int mi=0; mi<4; mi++)
                #pragma unroll
                for (int ni=0; ni<4; ni++){
                    mma16816(acc[mi][ni], af[mi],  bf[ni]);
                    mma16816(acc[mi][ni], af[mi],  bf2[ni]);
                    mma16816(acc[mi][ni], af2[mi], bf[ni]);
                }
        }
        __syncthreads();
    }

    int tr = lane >> 2, tc = (lane & 3) * 2;
    #pragma unroll
    for (int mi=0; mi<4; mi++){
        #pragma unroll
        for (int ni=0; ni<4; ni++){
            int row = bm0 + wm*64 + mi*16 + tr;
            int col = bn0 + wn*32 + ni*8 + tc;
            float* a = acc[mi][ni];
            float b0 = bias[col], b1 = bias[col+1];
            float c0 = cG[col],  c1 = cG[col+1];
            float r0 = rsG[row], r8 = rsG[row+8];
            *(float2*)(Cout + (long)row*DD + col) =
                make_float2(tanhf(r0*(a[0]+c0)+b0), tanhf(r0*(a[1]+c1)+b1));
            *(float2*)(Cout + (long)(row+8)*DD + col) =
                make_float2(tanhf(r8*(a[2]+c0)+b0), tanhf(r8*(a[3]+c1)+b1));
        }
    }
}

// ---------------- rc[b,e] = 1 / sum of column partials ------------------------
__global__ void __launch_bounds__(256) rc_kernel(){
    int i = blockIdx.x*256 + threadIdx.x;       // 0..16383
    int b = i >> 12, e = i & (SS-1);
    const float* p = g_cpart + (long)b*32*SS + e;
    float s = 0.f;
    #pragma unroll
    for (int t = 0; t < 32; t++) s += p[(long)t*SS];
    g_rc[i] = 1.0f/s;
}

// ---------------- rowsum: rs[b,s] = sum_e E[b,s,e] * rc[b,e] ------------------
__global__ void __launch_bounds__(256) rowsum_kernel(){
    __shared__ float rcs[SS];
    int b = blockIdx.y;
    for (int i = threadIdx.x; i < SS; i += 256) rcs[i] = g_rc[b*SS + i];
    __syncthreads();
    int lane = threadIdx.x & 31, warp = threadIdx.x >> 5;
    int r = blockIdx.x*8 + warp;
    const uint4* row = (const uint4*)(g_E + ((long)b*SS + r)*(long)SS);
    float s = 0.f;
    #pragma unroll
    for (int it = 0; it < 16; it++){
        int j = it*32 + lane;
        uint4 v = row[j];
        const float4* c4 = (const float4*)(rcs + 8*j);
        float4 ca = c4[0], cb = c4[1];
        float2 f0 = __half22float2(*(const __half2*)&v.x);
        float2 f1 = __half22float2(*(const __half2*)&v.y);
        float2 f2 = __half22float2(*(const __half2*)&v.z);
        float2 f3 = __half22float2(*(const __half2*)&v.w);
        s += f0.x*ca.x + f0.y*ca.y + f1.x*ca.z + f1.y*ca.w
           + f2.x*cb.x + f2.y*cb.y + f3.x*cb.z + f3.y*cb.w;
    }
    #pragma unroll
    for (int o = 16; o; o >>= 1) s += __shfl_xor_sync(0xffffffffu, s, o);
    if (lane == 0) g_rs[b*SS + r] = s;
}

// ---------------- launch -----------------------------------------------------
extern "C" void kernel_launch(void* const* d_in, const int* in_sizes, int n_in,
                              void* d_out, int out_size)
{
    const float* xs = (const float*)d_in[0];
    const float* Wk = (const float*)d_in[1]; const float* bk = (const float*)d_in[2];
    const float* Wq = (const float*)d_in[3]; const float* bq = (const float*)d_in[4];
    const float* Wv = (const float*)d_in[5]; const float* bv = (const float*)d_in[6];
    const float* Wl = (const float*)d_in[7]; const float* bl = (const float*)d_in[8];

    void *p_xhi,*p_xlo,*p_KQ,*p_E,*p_bkq,*p_Wkq;
    void *p_Mhi,*p_Mlo,*p_rs,*p_c;
    cudaGetSymbolAddress(&p_xhi, g_xhi);   cudaGetSymbolAddress(&p_xlo, g_xlo);
    cudaGetSymbolAddress(&p_KQ,  g_KQ);    cudaGetSymbolAddress(&p_E,   g_E);
    cudaGetSymbolAddress(&p_bkq, g_bkq);   cudaGetSymbolAddress(&p_Wkq, g_Wkq);
    cudaGetSymbolAddress(&p_Mhi, g_Mhi);   cudaGetSymbolAddress(&p_Mlo, g_Mlo);
    cudaGetSymbolAddress(&p_rs,  g_rs);    cudaGetSymbolAddress(&p_c,   g_c);

    // pipelined plain: 2 stages x (A+B) x 128*72 halfs = 73728 B
    const size_t smemPipe  = (size_t)4*Bb_M*LDS_P*sizeof(__nv_bfloat16);  // 73728
    const size_t smemSplit = (size_t)4*Bb_M*LDS_S*sizeof(__nv_bfloat16);  // 73728

    cudaFuncSetAttribute((const void*)gemm_pipe<0>,
                         cudaFuncAttributeMaxDynamicSharedMemorySize, (int)smemPipe);
    cudaFuncSetAttribute((const void*)gemm_pipe<2>,
                         cudaFuncAttributeMaxDynamicSharedMemorySize, (int)smemPipe);
    cudaFuncSetAttribute((const void*)gemm_split,
                         cudaFuncAttributeMaxDynamicSharedMemorySize, (int)smemSplit);

    // 1. prep (vectorized) + M = Wl@Wv split + c = Wl@bv
    prep_kernel<<<(BSD/4 + 255)/256, 256>>>(xs, Wk, Wq, bk, bq);
    matM_kernel<<<dim3(DD/16, DD/16), dim3(16,16)>>>(Wl, Wv);
    cvec_kernel<<<DD/8, 256>>>(Wl, bv);

    // 2. merged K|Q projection -> g_KQ [16384, 1024]
    dim3 gkq(2*DD/Bb_N, (BB*SS)/Bb_M, 1);   // (8, 128)
    gemm_pipe<0><<<gkq, 256, smemPipe>>>(
        (const __nv_bfloat16*)p_xhi, (const __nv_bfloat16*)p_Wkq,
        (const float*)p_bkq, p_KQ, DD, DD, DD, 2*DD, 0, 0, 0);

    // 3. E = exp(K Q^T / 512) fp16 + fused fp16-rounded column partials
    dim3 gq(SS/Bb_N, SS/Bb_M, BB);          // (32, 32, 4)
    gemm_pipe<2><<<gq, 256, smemPipe>>>(
        (const __nv_bfloat16*)p_KQ, (const __nv_bfloat16*)p_KQ + DD,
        nullptr, p_E, DD, 2*DD, 2*DD, SS,
        (long)SS*2*DD, (long)SS*2*DD, (long)SS*SS);

    // 4. rc = 1/colsum; 5. rowsum (vectorized)
    rc_kernel<<<BB*SS/256, 256>>>();
    rowsum_kernel<<<dim3(SS/8, BB), 256>>>();

    // 6. out = tanh(rs*(x M^T + c) + bl)  — single fused split GEMM
    dim3 gp(DD/Bb_N, (BB*SS)/Bb_M, 1);      // (4, 128)
    gemm_split<<<gp, 256, smemSplit>>>(
        (const __nv_bfloat16*)p_xhi, (const __nv_bfloat16*)p_xlo,
        (const __nv_bfloat16*)p_Mhi, (const __nv_bfloat16*)p_Mlo,
        bl, (float*)d_out, (const float*)p_rs, (const float*)p_c);
}